// round 12
// baseline (speedup 1.0000x reference)
#include <cuda_runtime.h>
#include <cstdint>

// ---------------------------------------------------------------------------
// HDCTokenEncoder: out[b,i,d] = item_memory[tok[b,i]][(d - i) mod D] * (1/sqrt(D))
// item_memory entries are exactly +/-1 => row L2 norm == sqrt(D) == 100 exactly,
// so normalization is the constant 0.01f (applied once while staging SMEM).
//
// R12 = R11 tile body + persistent-block WORK STEALING. 4096 (token, class)
// tiles are pulled from a global atomic counter by 608 persistent CTAs
// (4/SM), removing wave-boundary idle time: each wave previously waited on
// its slowest CTA (tile work ~ Poisson(4) rows). Tiles are independent, so
// the dynamic assignment cannot affect the output (deterministic).
//
// Tile (t, y): c = y>>2, m = y&3. Positions i in [512c, 512c+512) with
// i % 4 == m, across all 8 batches. Each int4 of the token array holds
// exactly one candidate (element m) -> fully coalesced scan.
// All rows share m = r mod 4 -> staged row is pre-rotated by m:
//   T[d] = 0.01 * row[(d - m) mod D]
// so each output row is a whole-quad rotation: load T[(g - q0) mod D4],
// store at quad g (sector-aligned streaming STG.128), q0 = (r - m)/4.
// ---------------------------------------------------------------------------

#define HDC_D      10000
#define HDC_D4     2500              // D / 4
#define HDC_S      2048              // sequence length (power of two)
#define HDC_V      256
#define NCLASS     16                // 4 chunks x 4 residues
#define NTILES     (HDC_V * NCLASS)  // 4096
#define CHUNK      512               // positions per chunk (S / 4)
#define CAND_VEC   1024              // int4 candidates per tile (8 batches x 128)
#define NTHR       512
#define NBLOCKS    608               // 4 CTAs/SM x 152 SMs (GB300)

__device__ unsigned int g_tile_ctr;

__global__ void k_reset() { g_tile_ctr = 0u; }

template <int OFS>
__device__ __forceinline__ float4 blend(float4 A, float4 B) {
    if (OFS == 0) return A;
    if (OFS == 1) return make_float4(A.y, A.z, A.w, B.x);
    if (OFS == 2) return make_float4(A.z, A.w, B.x, B.y);
    return make_float4(A.w, B.x, B.y, B.z);
}

// Stage T[d] = 0.01 * s[(d - m) mod D]; OFS = (-m) mod 4.
template <int OFS>
__device__ __forceinline__ void stage(const float4* __restrict__ sq,
                                      float4* __restrict__ T4, int m) {
    const float scale = 0.01f;
    for (int g = threadIdx.x; g < HDC_D4; g += NTHR) {
        int s0 = 4 * g - m;
        if (s0 < 0) s0 += HDC_D;
        int qa = s0 >> 2;
        float4 v;
        if (OFS == 0) {
            v = __ldg(&sq[qa]);
        } else {
            int qb = qa + 1;
            if (qb == HDC_D4) qb = 0;
            v = blend<OFS>(__ldg(&sq[qa]), __ldg(&sq[qb]));
        }
        v.x *= scale; v.y *= scale; v.z *= scale; v.w *= scale;
        T4[g] = v;
    }
}

// One row, unroll-2 batched LDS: out quad g <- T quad (g - q0) mod D4.
__device__ __forceinline__ void emit1(const float4* __restrict__ T4,
                                      float4* __restrict__ dst, int q0) {
    int qa = (int)threadIdx.x - q0;
    if (qa < 0) qa += HDC_D4;
    int g = threadIdx.x;
    for (; g + NTHR < HDC_D4; g += 2 * NTHR) {
        int qb = qa + NTHR;
        if (qb >= HDC_D4) qb -= HDC_D4;
        float4 v0 = T4[qa];              // two independent LDS.128
        float4 v1 = T4[qb];
        __stcs(dst + g, v0);             // two aligned streaming STG.128
        __stcs(dst + g + NTHR, v1);
        qa = qb + NTHR;
        if (qa >= HDC_D4) qa -= HDC_D4;
    }
    if (g < HDC_D4)
        __stcs(dst + g, T4[qa]);
}

__global__ __launch_bounds__(NTHR, 4) void k_encode(const int* __restrict__ tok,
                                                    const float* __restrict__ im,
                                                    float* __restrict__ out) {
    __shared__ float4 T4[HDC_D4];      // 40 KB pre-rotated, pre-scaled row
    __shared__ int    list[CAND_VEC];  // 4 KB: matching flat positions
    __shared__ int    nmatch;
    __shared__ int    s_tile;

    const int4* tok4 = reinterpret_cast<const int4*>(tok);

    for (;;) {
        // Grab next tile. Safe vs. stragglers of the previous iteration:
        // they only read list[]/T4[] (orders via the barrier below).
        if (threadIdx.x == 0) {
            s_tile = (int)atomicAdd(&g_tile_ctr, 1u);
            nmatch = 0;
        }
        __syncthreads();
        const int tile = s_tile;
        if (tile >= NTILES) return;

        const int t = tile >> 4;       // token id
        const int y = tile & 15;       // class
        const int c = y >> 2;          // chunk index
        const int m = y & 3;           // shared r mod 4 for all rows here

        // Phase 1: coalesced scan (2 LDG.128 per thread).
        const int vbase = c * (CHUNK / 4);   // c * 128
        for (int q = threadIdx.x; q < CAND_VEC; q += NTHR) {
            int b     = q >> 7;
            int local = q & 127;
            int4 vec  = __ldg(&tok4[b * (HDC_S / 4) + vbase + local]);
            int v = (m < 2) ? (m == 0 ? vec.x : vec.y)
                            : (m == 2 ? vec.z : vec.w);
            if (v == t) {
                int k = atomicAdd(&nmatch, 1);
                list[k] = b * HDC_S + c * CHUNK + 4 * local + m;
            }
        }
        // No barrier: staging is independent of the scan; the single barrier
        // below orders both list[] and T4[] before emission.

        // Phase 2: stage the pre-rotated, pre-scaled row (blend paid once).
        const float4* sq = reinterpret_cast<const float4*>(im + (size_t)t * HDC_D);
        switch ((4 - m) & 3) {
            case 0: stage<0>(sq, T4, m); break;
            case 1: stage<1>(sq, T4, m); break;
            case 2: stage<2>(sq, T4, m); break;
            default: stage<3>(sq, T4, m); break;
        }
        __syncthreads();

        const int n = nmatch;

        // Phase 3: emit rows; each is a whole-quad rotation of T.
        for (int p = 0; p < n; ++p) {
            const int bs = list[p];
            const int q0 = ((bs & (HDC_S - 1)) - m) >> 2;
            emit1(T4, reinterpret_cast<float4*>(out + (size_t)bs * HDC_D), q0);
        }
        __syncthreads();   // all reads of list[]/T4[] done before next tile
    }
}

extern "C" void kernel_launch(void* const* d_in, const int* in_sizes, int n_in,
                              void* d_out, int out_size) {
    const int*   tok = (const int*)d_in[0];     // (B, S) int32
    const float* im  = (const float*)d_in[1];   // (V, D) float32
    float*       out = (float*)d_out;           // (B, S, D) float32
    (void)in_sizes; (void)n_in; (void)out_size;

    k_reset<<<1, 1>>>();
    k_encode<<<NBLOCKS, NTHR>>>(tok, im, out);
}

// round 13
// speedup vs baseline: 1.0065x; 1.0065x over previous
#include <cuda_runtime.h>
#include <cstdint>

// ---------------------------------------------------------------------------
// HDCTokenEncoder: out[b,i,d] = item_memory[tok[b,i]][(d - i) mod D] * (1/sqrt(D))
// item_memory entries are exactly +/-1 => row L2 norm == sqrt(D) == 100 exactly,
// so normalization is the constant 0.01f (applied once while staging SMEM).
//
// R13 = R11 body with 384-thread blocks at 5 CTAs/SM (221KB smem/SM). More
// co-resident CTAs cover each other's non-storing prologues (scan + 40KB
// staging), smoothing the DRAM write stream -- the mechanism the persistent
// R12 variant destroyed (serial barrier-drained tiles regressed to 103.6).
//
// Classes: y in [0,16) -> (c = y>>2, m = y&3). Block (t, y) handles positions
// i in [512c, 512c+512) with i % 4 == m, across all 8 batches. Each int4 of
// the token array holds exactly one candidate (element m) -> coalesced scan.
// All rows share m = r mod 4 -> staged row is pre-rotated by m:
//   T[d] = 0.01 * row[(d - m) mod D]
// so each output row is a whole-quad rotation: load T[(g - q0) mod D4], store
// at quad g (sector-aligned streaming STG.128), q0 = (r - m)/4.
// ---------------------------------------------------------------------------

#define HDC_D      10000
#define HDC_D4     2500              // D / 4
#define HDC_S      2048              // sequence length (power of two)
#define HDC_V      256
#define NCLASS     16                // 4 chunks x 4 residues
#define CHUNK      512               // positions per chunk (S / 4)
#define CAND_VEC   1024              // int4 candidates per block (8 batches x 128)
#define NTHR       384               // 12 warps; 5 CTAs/SM (smem 221KB, warps 60)

template <int OFS>
__device__ __forceinline__ float4 blend(float4 A, float4 B) {
    if (OFS == 0) return A;
    if (OFS == 1) return make_float4(A.y, A.z, A.w, B.x);
    if (OFS == 2) return make_float4(A.z, A.w, B.x, B.y);
    return make_float4(A.w, B.x, B.y, B.z);
}

// Stage T[d] = 0.01 * s[(d - m) mod D]; OFS = (-m) mod 4.
template <int OFS>
__device__ __forceinline__ void stage(const float4* __restrict__ sq,
                                      float4* __restrict__ T4, int m) {
    const float scale = 0.01f;
    for (int g = threadIdx.x; g < HDC_D4; g += NTHR) {
        int s0 = 4 * g - m;
        if (s0 < 0) s0 += HDC_D;
        int qa = s0 >> 2;
        float4 v;
        if (OFS == 0) {
            v = __ldg(&sq[qa]);
        } else {
            int qb = qa + 1;
            if (qb == HDC_D4) qb = 0;
            v = blend<OFS>(__ldg(&sq[qa]), __ldg(&sq[qb]));
        }
        v.x *= scale; v.y *= scale; v.z *= scale; v.w *= scale;
        T4[g] = v;
    }
}

// One row, unroll-2 with batched LDS: out quad g <- T quad (g - q0) mod D4.
__device__ __forceinline__ void emit1(const float4* __restrict__ T4,
                                      float4* __restrict__ dst, int q0) {
    int qa = (int)threadIdx.x - q0;
    if (qa < 0) qa += HDC_D4;
    int g = threadIdx.x;
    for (; g + NTHR < HDC_D4; g += 2 * NTHR) {
        int qb = qa + NTHR;
        if (qb >= HDC_D4) qb -= HDC_D4;
        float4 v0 = T4[qa];              // two independent LDS.128
        float4 v1 = T4[qb];
        __stcs(dst + g, v0);             // two aligned streaming STG.128
        __stcs(dst + g + NTHR, v1);
        qa = qb + NTHR;
        if (qa >= HDC_D4) qa -= HDC_D4;
    }
    if (g < HDC_D4)
        __stcs(dst + g, T4[qa]);
}

__global__ __launch_bounds__(NTHR, 5) void k_encode(const int* __restrict__ tok,
                                                    const float* __restrict__ im,
                                                    float* __restrict__ out) {
    __shared__ float4 T4[HDC_D4];      // 40 KB pre-rotated, pre-scaled row
    __shared__ int    list[CAND_VEC];  // 4 KB: matching flat positions
    __shared__ int    nmatch;

    const int t = blockIdx.x;          // token id
    const int y = blockIdx.y;          // class
    const int c = y >> 2;              // chunk index
    const int m = y & 3;               // shared r mod 4 for all rows here

    if (threadIdx.x == 0) nmatch = 0;
    __syncthreads();

    // Phase 1: coalesced scan.
    // int4 vector q in [0,1024): b = q>>7, local = q&127,
    // candidate position i = 512c + 4*local + m, flat bs = 2048b + i.
    const int4* tok4 = reinterpret_cast<const int4*>(tok);
    const int vbase = c * (CHUNK / 4);   // c * 128
    for (int q = threadIdx.x; q < CAND_VEC; q += NTHR) {
        int b     = q >> 7;
        int local = q & 127;
        int4 vec  = __ldg(&tok4[b * (HDC_S / 4) + vbase + local]);
        int v = (m < 2) ? (m == 0 ? vec.x : vec.y)
                        : (m == 2 ? vec.z : vec.w);
        if (v == t) {
            int k = atomicAdd(&nmatch, 1);
            list[k] = b * HDC_S + c * CHUNK + 4 * local + m;
        }
    }
    // No barrier here: staging is independent of the scan; the single barrier
    // below orders both list[] and T4[] before emission.

    // Phase 2: stage the pre-rotated, pre-scaled row (blend paid once).
    const float4* sq = reinterpret_cast<const float4*>(im + (size_t)t * HDC_D);
    switch ((4 - m) & 3) {
        case 0: stage<0>(sq, T4, m); break;
        case 1: stage<1>(sq, T4, m); break;
        case 2: stage<2>(sq, T4, m); break;
        default: stage<3>(sq, T4, m); break;
    }
    __syncthreads();

    const int n = nmatch;

    // Phase 3: emit rows; each is a whole-quad rotation of T.
    for (int p = 0; p < n; ++p) {
        const int bs = list[p];
        const int q0 = ((bs & (HDC_S - 1)) - m) >> 2;   // whole-quad rotation
        emit1(T4, reinterpret_cast<float4*>(out + (size_t)bs * HDC_D), q0);
    }
}

extern "C" void kernel_launch(void* const* d_in, const int* in_sizes, int n_in,
                              void* d_out, int out_size) {
    const int*   tok = (const int*)d_in[0];     // (B, S) int32
    const float* im  = (const float*)d_in[1];   // (V, D) float32
    float*       out = (float*)d_out;           // (B, S, D) float32
    (void)in_sizes; (void)n_in; (void)out_size;

    dim3 grid(HDC_V, NCLASS);
    k_encode<<<grid, NTHR>>>(tok, im, out);
}

// round 14
// speedup vs baseline: 1.0147x; 1.0082x over previous
#include <cuda_runtime.h>
#include <cstdint>

// ---------------------------------------------------------------------------
// HDCTokenEncoder: out[b,i,d] = item_memory[tok[b,i]][(d - i) mod D] * (1/sqrt(D))
// item_memory entries are exactly +/-1 => row L2 norm == sqrt(D) == 100 exactly,
// so normalization is the constant 0.01f (applied once while staging SMEM).
//
// R14 = R11 (best: 512 thr, 4 CTAs/SM, coalesced scan, pre-rotated staging,
// unroll-2 aligned streaming emission) + warp-ballot scan compaction:
// each warp owns a 64-entry list segment and compacts matches with
// ballot/popc -- no smem atomics, and the pre-scan barrier is deleted
// (single barrier before emission orders list/wcount/T4).
//
// Classes: y in [0,16) -> (c = y>>2, m = y&3). Block (t, y) handles positions
// i in [512c, 512c+512) with i % 4 == m, across all 8 batches. Each int4 of
// the token array holds exactly one candidate (element m) -> coalesced scan.
// All rows share m = r mod 4 -> staged row is pre-rotated by m:
//   T[d] = 0.01 * row[(d - m) mod D]
// so each output row is a whole-quad rotation: load T[(g - q0) mod D4], store
// at quad g (sector-aligned streaming STG.128), q0 = (r - m)/4.
// ---------------------------------------------------------------------------

#define HDC_D      10000
#define HDC_D4     2500              // D / 4
#define HDC_S      2048              // sequence length (power of two)
#define HDC_V      256
#define NCLASS     16                // 4 chunks x 4 residues
#define CHUNK      512               // positions per chunk (S / 4)
#define CAND_VEC   1024              // int4 candidates per block (8 batches x 128)
#define NTHR       512
#define NWARP      (NTHR / 32)       // 16 warps; 64 candidates per warp

template <int OFS>
__device__ __forceinline__ float4 blend(float4 A, float4 B) {
    if (OFS == 0) return A;
    if (OFS == 1) return make_float4(A.y, A.z, A.w, B.x);
    if (OFS == 2) return make_float4(A.z, A.w, B.x, B.y);
    return make_float4(A.w, B.x, B.y, B.z);
}

// Stage T[d] = 0.01 * s[(d - m) mod D]; OFS = (-m) mod 4.
template <int OFS>
__device__ __forceinline__ void stage(const float4* __restrict__ sq,
                                      float4* __restrict__ T4, int m) {
    const float scale = 0.01f;
    for (int g = threadIdx.x; g < HDC_D4; g += NTHR) {
        int s0 = 4 * g - m;
        if (s0 < 0) s0 += HDC_D;
        int qa = s0 >> 2;
        float4 v;
        if (OFS == 0) {
            v = __ldg(&sq[qa]);
        } else {
            int qb = qa + 1;
            if (qb == HDC_D4) qb = 0;
            v = blend<OFS>(__ldg(&sq[qa]), __ldg(&sq[qb]));
        }
        v.x *= scale; v.y *= scale; v.z *= scale; v.w *= scale;
        T4[g] = v;
    }
}

// One row, unroll-2 with batched LDS: out quad g <- T quad (g - q0) mod D4.
__device__ __forceinline__ void emit1(const float4* __restrict__ T4,
                                      float4* __restrict__ dst, int q0) {
    int qa = (int)threadIdx.x - q0;
    if (qa < 0) qa += HDC_D4;
    int g = threadIdx.x;
    for (; g + NTHR < HDC_D4; g += 2 * NTHR) {
        int qb = qa + NTHR;
        if (qb >= HDC_D4) qb -= HDC_D4;
        float4 v0 = T4[qa];              // two independent LDS.128
        float4 v1 = T4[qb];
        __stcs(dst + g, v0);             // two aligned streaming STG.128
        __stcs(dst + g + NTHR, v1);
        qa = qb + NTHR;
        if (qa >= HDC_D4) qa -= HDC_D4;
    }
    if (g < HDC_D4)
        __stcs(dst + g, T4[qa]);
}

__global__ __launch_bounds__(NTHR, 4) void k_encode(const int* __restrict__ tok,
                                                    const float* __restrict__ im,
                                                    float* __restrict__ out) {
    __shared__ float4 T4[HDC_D4];          // 40 KB pre-rotated, pre-scaled row
    __shared__ int    list[NWARP * 64];    // 4 KB: per-warp match segments
    __shared__ int    wcount[NWARP];       // per-warp match counts

    const int t = blockIdx.x;          // token id
    const int y = blockIdx.y;          // class
    const int c = y >> 2;              // chunk index
    const int m = y & 3;               // shared r mod 4 for all rows here

    const int w    = threadIdx.x >> 5;
    const int lane = threadIdx.x & 31;

    // Phase 1: coalesced scan with warp-ballot compaction (no atomics, no
    // pre-scan barrier). int4 vector q in [0,1024): b = q>>7, local = q&127,
    // candidate position i = 512c + 4*local + m, flat bs = 2048b + i.
    const int4* tok4 = reinterpret_cast<const int4*>(tok);
    const int vbase = c * (CHUNK / 4);   // c * 128
    int base = 0;
    for (int q = threadIdx.x; q < CAND_VEC; q += NTHR) {
        int b     = q >> 7;
        int local = q & 127;
        int4 vec  = __ldg(&tok4[b * (HDC_S / 4) + vbase + local]);
        int v = (m < 2) ? (m == 0 ? vec.x : vec.y)
                        : (m == 2 ? vec.z : vec.w);
        bool match  = (v == t);
        unsigned mk = __ballot_sync(0xFFFFFFFFu, match);
        if (match) {
            int pos = __popc(mk & ((1u << lane) - 1u));
            list[(w << 6) + base + pos] = b * HDC_S + c * CHUNK + 4 * local + m;
        }
        base += __popc(mk);
    }
    if (lane == 0) wcount[w] = base;
    // No barrier here: staging is independent; the single barrier below
    // orders list[], wcount[], and T4[] before emission.

    // Phase 2: stage the pre-rotated, pre-scaled row (blend paid once).
    const float4* sq = reinterpret_cast<const float4*>(im + (size_t)t * HDC_D);
    switch ((4 - m) & 3) {
        case 0: stage<0>(sq, T4, m); break;
        case 1: stage<1>(sq, T4, m); break;
        case 2: stage<2>(sq, T4, m); break;
        default: stage<3>(sq, T4, m); break;
    }
    __syncthreads();

    // Phase 3: emit rows from each warp segment; each row is a whole-quad
    // rotation of T, stored at aligned quad g.
    for (int ws = 0; ws < NWARP; ++ws) {
        const int cnt = wcount[ws];
        for (int p = 0; p < cnt; ++p) {
            const int bs = list[(ws << 6) + p];
            const int q0 = ((bs & (HDC_S - 1)) - m) >> 2;
            emit1(T4, reinterpret_cast<float4*>(out + (size_t)bs * HDC_D), q0);
        }
    }
}

extern "C" void kernel_launch(void* const* d_in, const int* in_sizes, int n_in,
                              void* d_out, int out_size) {
    const int*   tok = (const int*)d_in[0];     // (B, S) int32
    const float* im  = (const float*)d_in[1];   // (V, D) float32
    float*       out = (float*)d_out;           // (B, S, D) float32
    (void)in_sizes; (void)n_in; (void)out_size;

    dim3 grid(HDC_V, NCLASS);
    k_encode<<<grid, NTHR>>>(tok, im, out);
}

// round 15
// speedup vs baseline: 1.0286x; 1.0137x over previous
#include <cuda_runtime.h>
#include <cstdint>

// ---------------------------------------------------------------------------
// HDCTokenEncoder: out[b,i,d] = item_memory[tok[b,i]][(d - i) mod D] * (1/sqrt(D))
// item_memory entries are exactly +/-1 => row L2 norm == sqrt(D) == 100 exactly,
// so normalization is the constant 0.01f (applied once while staging SMEM).
//
// FINAL (converged over 14 rounds at the HBM3e pure-write ceiling, ~6.1TB/s):
//  - 512 threads, __launch_bounds__(512,4): 4 CTAs/SM, 92% occupancy.
//  - Classes: y in [0,16) -> (c = y>>2, m = y&3). Block (t, y) handles
//    positions i in [512c, 512c+512) with i % 4 == m, across all 8 batches.
//    Each int4 of the token array holds exactly one candidate (element m)
//    -> fully coalesced scan (2 LDG.128/thread), smem-atomic compaction.
//  - All rows in a block share m = r mod 4 -> staged row is pre-rotated:
//      T[d] = 0.01 * row[(d - m) mod D]
//    so every output row is a whole-quad (float4) rotation of T.
//  - Emission: load T[(g - q0) mod D4] (LDS.128), store at quad g -- keeps
//    every warp's 512B store chunk sector-aligned (store-side rotation was
//    proven to cost ~5% DRAM efficiency). Unroll-2 with batched LDS.
//  - __stcs streaming stores: output is written once, never re-read.
//  - Single barrier: scan and staging are independent; one __syncthreads
//    orders list[]/nmatch/T4[] before emission.
//
// Probed and rejected: TMA bulk S2G (drain tails, -11%), store-side rotation
// (misaligned sectors, -5%), persistent work-stealing (-3%), 5 CTAs/SM (-2%),
// row-pairing / ballot compaction (neutral-to-negative).
// ---------------------------------------------------------------------------

#define HDC_D      10000
#define HDC_D4     2500              // D / 4
#define HDC_S      2048              // sequence length (power of two)
#define HDC_V      256
#define NCLASS     16                // 4 chunks x 4 residues
#define CHUNK      512               // positions per chunk (S / 4)
#define CAND_VEC   1024              // int4 candidates per block (8 batches x 128)
#define NTHR       512

template <int OFS>
__device__ __forceinline__ float4 blend(float4 A, float4 B) {
    if (OFS == 0) return A;
    if (OFS == 1) return make_float4(A.y, A.z, A.w, B.x);
    if (OFS == 2) return make_float4(A.z, A.w, B.x, B.y);
    return make_float4(A.w, B.x, B.y, B.z);
}

// Stage T[d] = 0.01 * s[(d - m) mod D]; OFS = (-m) mod 4.
template <int OFS>
__device__ __forceinline__ void stage(const float4* __restrict__ sq,
                                      float4* __restrict__ T4, int m) {
    const float scale = 0.01f;
    for (int g = threadIdx.x; g < HDC_D4; g += NTHR) {
        int s0 = 4 * g - m;
        if (s0 < 0) s0 += HDC_D;
        int qa = s0 >> 2;
        float4 v;
        if (OFS == 0) {
            v = __ldg(&sq[qa]);
        } else {
            int qb = qa + 1;
            if (qb == HDC_D4) qb = 0;
            v = blend<OFS>(__ldg(&sq[qa]), __ldg(&sq[qb]));
        }
        v.x *= scale; v.y *= scale; v.z *= scale; v.w *= scale;
        T4[g] = v;
    }
}

// One row, unroll-2 with batched LDS: out quad g <- T quad (g - q0) mod D4.
__device__ __forceinline__ void emit1(const float4* __restrict__ T4,
                                      float4* __restrict__ dst, int q0) {
    int qa = (int)threadIdx.x - q0;
    if (qa < 0) qa += HDC_D4;
    int g = threadIdx.x;
    for (; g + NTHR < HDC_D4; g += 2 * NTHR) {
        int qb = qa + NTHR;
        if (qb >= HDC_D4) qb -= HDC_D4;
        float4 v0 = T4[qa];              // two independent LDS.128
        float4 v1 = T4[qb];
        __stcs(dst + g, v0);             // two aligned streaming STG.128
        __stcs(dst + g + NTHR, v1);
        qa = qb + NTHR;
        if (qa >= HDC_D4) qa -= HDC_D4;
    }
    if (g < HDC_D4)
        __stcs(dst + g, T4[qa]);
}

__global__ __launch_bounds__(NTHR, 4) void k_encode(const int* __restrict__ tok,
                                                    const float* __restrict__ im,
                                                    float* __restrict__ out) {
    __shared__ float4 T4[HDC_D4];      // 40 KB pre-rotated, pre-scaled row
    __shared__ int    list[CAND_VEC];  // 4 KB: matching flat positions
    __shared__ int    nmatch;

    const int t = blockIdx.x;          // token id
    const int y = blockIdx.y;          // class
    const int c = y >> 2;              // chunk index
    const int m = y & 3;               // shared r mod 4 for all rows here

    if (threadIdx.x == 0) nmatch = 0;
    __syncthreads();

    // Phase 1: coalesced scan (2 LDG.128 per thread).
    // int4 vector q in [0,1024): b = q>>7, local = q&127,
    // candidate position i = 512c + 4*local + m, flat bs = 2048b + i.
    const int4* tok4 = reinterpret_cast<const int4*>(tok);
    const int vbase = c * (CHUNK / 4);   // c * 128
    for (int q = threadIdx.x; q < CAND_VEC; q += NTHR) {
        int b     = q >> 7;
        int local = q & 127;
        int4 vec  = __ldg(&tok4[b * (HDC_S / 4) + vbase + local]);
        int v = (m < 2) ? (m == 0 ? vec.x : vec.y)
                        : (m == 2 ? vec.z : vec.w);
        if (v == t) {
            int k = atomicAdd(&nmatch, 1);
            list[k] = b * HDC_S + c * CHUNK + 4 * local + m;
        }
    }
    // No barrier here: staging is independent of the scan; the single barrier
    // below orders both list[] and T4[] before emission.

    // Phase 2: stage the pre-rotated, pre-scaled row (blend paid once).
    const float4* sq = reinterpret_cast<const float4*>(im + (size_t)t * HDC_D);
    switch ((4 - m) & 3) {
        case 0: stage<0>(sq, T4, m); break;
        case 1: stage<1>(sq, T4, m); break;
        case 2: stage<2>(sq, T4, m); break;
        default: stage<3>(sq, T4, m); break;
    }
    __syncthreads();

    const int n = nmatch;

    // Phase 3: emit rows; each is a whole-quad rotation of T.
    for (int p = 0; p < n; ++p) {
        const int bs = list[p];
        const int q0 = ((bs & (HDC_S - 1)) - m) >> 2;   // whole-quad rotation
        emit1(T4, reinterpret_cast<float4*>(out + (size_t)bs * HDC_D), q0);
    }
}

extern "C" void kernel_launch(void* const* d_in, const int* in_sizes, int n_in,
                              void* d_out, int out_size) {
    const int*   tok = (const int*)d_in[0];     // (B, S) int32
    const float* im  = (const float*)d_in[1];   // (V, D) float32
    float*       out = (float*)d_out;           // (B, S, D) float32
    (void)in_sizes; (void)n_in; (void)out_size;

    dim3 grid(HDC_V, NCLASS);
    k_encode<<<grid, NTHR>>>(tok, im, out);
}